// round 1
// baseline (speedup 1.0000x reference)
#include <cuda_runtime.h>
#include <cuda_bf16.h>

#define D 784
#define H 1024
#define BATCH 1024
#define THREADS 128
#define HPT 8   // h-values per thread (128*8 = 1024 = H)

// Scratch (no allocations allowed): transposed W and fused bias.
__device__ float g_WT[D * H];   // g_WT[i*H + h] = W[h*D + i]
__device__ float g_bias[D];     // bias[i] = b[i] + 0.5 * sum_h V[i,h]

__device__ __forceinline__ float fast_tanh(float x) {
    float y;
    asm("tanh.approx.f32 %0, %1;" : "=f"(y) : "f"(x));
    return y;
}

// ---------------------------------------------------------------------------
// Prep 1: tiled transpose W[H,D] -> g_WT[D,H]
// ---------------------------------------------------------------------------
__global__ void transpose_W(const float* __restrict__ W) {
    __shared__ float tile[32][33];
    int ix = blockIdx.x * 32 + threadIdx.x;   // D index (contiguous in W)
    int iy = blockIdx.y * 32 + threadIdx.y;   // H index
    #pragma unroll
    for (int j = 0; j < 32; j += 8) {
        int y = iy + j;
        if (ix < D && y < H)
            tile[threadIdx.y + j][threadIdx.x] = W[y * D + ix];
    }
    __syncthreads();
    int ox = blockIdx.y * 32 + threadIdx.x;   // H index (contiguous in WT)
    int oy = blockIdx.x * 32 + threadIdx.y;   // D index
    #pragma unroll
    for (int j = 0; j < 32; j += 8) {
        int y = oy + j;
        if (ox < H && y < D)
            g_WT[y * H + ox] = tile[threadIdx.x][threadIdx.y + j];
    }
}

// ---------------------------------------------------------------------------
// Prep 2: bias[i] = b[i] + 0.5 * sum_h V[i,h]   (one warp per i)
// ---------------------------------------------------------------------------
__global__ void compute_bias(const float* __restrict__ V,
                             const float* __restrict__ bvec) {
    int i = blockIdx.x;
    int lane = threadIdx.x;
    float s = 0.0f;
    #pragma unroll
    for (int h = lane; h < H; h += 32) s += V[i * H + h];
    #pragma unroll
    for (int o = 16; o > 0; o >>= 1) s += __shfl_xor_sync(0xffffffffu, s, o);
    if (lane == 0) g_bias[i] = bvec[i] + 0.5f * s;
}

// ---------------------------------------------------------------------------
// Main: one CTA per batch row. A = a/2 lives in registers (8 per thread).
// Per step: tanh(A) -> dot with V row (warp-reduced, deferred to smem),
// A += WT_row * (x/2). No __syncthreads inside the 784-step loop.
// ---------------------------------------------------------------------------
__global__ void __launch_bounds__(THREADS)
nade_main(const float* __restrict__ pixels,
          const float* __restrict__ c,
          const float* __restrict__ V,
          float* __restrict__ out) {
    __shared__ float sx[D];            // 0.5 * pixels[b, :]
    __shared__ float sp[D * 4];        // per-step per-warp partials (4 warps)

    const int b    = blockIdx.x;
    const int t    = threadIdx.x;
    const int lane = t & 31;
    const int wid  = t >> 5;

    // Cooperative load of this row's pixels, pre-scaled by 0.5.
    for (int i = t; i < D; i += THREADS)
        sx[i] = 0.5f * pixels[b * D + i];

    // Accumulator init: A = c/2.
    float A[HPT];
    const float4* c4 = reinterpret_cast<const float4*>(c) + t * 2;
    {
        float4 c0 = c4[0];
        float4 c1 = c4[1];
        A[0] = 0.5f * c0.x; A[1] = 0.5f * c0.y; A[2] = 0.5f * c0.z; A[3] = 0.5f * c0.w;
        A[4] = 0.5f * c1.x; A[5] = 0.5f * c1.y; A[6] = 0.5f * c1.z; A[7] = 0.5f * c1.w;
    }
    __syncthreads();

    const float4* V4 = reinterpret_cast<const float4*>(V);
    const float4* W4 = reinterpret_cast<const float4*>(g_WT);
    const int base = t * 2;            // float4 index within a 256-float4 row

    #pragma unroll 2
    for (int i = 0; i < D; i++) {
        const int roff = i * (H / 4) + base;
        float4 v0 = V4[roff];
        float4 v1 = V4[roff + 1];
        float4 w0 = W4[roff];
        float4 w1 = W4[roff + 1];
        float xs = sx[i];

        float t0 = fast_tanh(A[0]);
        float t1 = fast_tanh(A[1]);
        float t2 = fast_tanh(A[2]);
        float t3 = fast_tanh(A[3]);
        float t4 = fast_tanh(A[4]);
        float t5 = fast_tanh(A[5]);
        float t6 = fast_tanh(A[6]);
        float t7 = fast_tanh(A[7]);

        float p;
        p = v0.x * t0;
        p = fmaf(v0.y, t1, p);
        p = fmaf(v0.z, t2, p);
        p = fmaf(v0.w, t3, p);
        p = fmaf(v1.x, t4, p);
        p = fmaf(v1.y, t5, p);
        p = fmaf(v1.z, t6, p);
        p = fmaf(v1.w, t7, p);

        A[0] = fmaf(w0.x, xs, A[0]);
        A[1] = fmaf(w0.y, xs, A[1]);
        A[2] = fmaf(w0.z, xs, A[2]);
        A[3] = fmaf(w0.w, xs, A[3]);
        A[4] = fmaf(w1.x, xs, A[4]);
        A[5] = fmaf(w1.y, xs, A[5]);
        A[6] = fmaf(w1.z, xs, A[6]);
        A[7] = fmaf(w1.w, xs, A[7]);

        // Warp reduce p (full 32-lane tree).
        p += __shfl_xor_sync(0xffffffffu, p, 16);
        p += __shfl_xor_sync(0xffffffffu, p, 8);
        p += __shfl_xor_sync(0xffffffffu, p, 4);
        p += __shfl_xor_sync(0xffffffffu, p, 2);
        p += __shfl_xor_sync(0xffffffffu, p, 1);
        if (lane == 0) sp[i * 4 + wid] = p;
    }

    __syncthreads();

    // Final cross-warp reduction + output. out[b, i] = bias[i] + 0.5 * sum.
    for (int i = t; i < D; i += THREADS) {
        float s = sp[i * 4 + 0] + sp[i * 4 + 1] + sp[i * 4 + 2] + sp[i * 4 + 3];
        out[b * D + i] = g_bias[i] + 0.5f * s;
    }
}

// ---------------------------------------------------------------------------
extern "C" void kernel_launch(void* const* d_in, const int* in_sizes, int n_in,
                              void* d_out, int out_size) {
    const float* pixels = (const float*)d_in[0];   // [1024, 784]
    const float* W      = (const float*)d_in[1];   // [1024, 784]
    const float* c      = (const float*)d_in[2];   // [1024]
    const float* V      = (const float*)d_in[3];   // [784, 1024]
    const float* bvec   = (const float*)d_in[4];   // [784]
    float* out          = (float*)d_out;           // [1024, 784]

    dim3 tb(32, 8);
    dim3 tg((D + 31) / 32, H / 32);
    transpose_W<<<tg, tb>>>(W);
    compute_bias<<<D, 32>>>(V, bvec);
    nade_main<<<BATCH, THREADS>>>(pixels, c, V, out);
}

// round 2
// speedup vs baseline: 1.0914x; 1.0914x over previous
#include <cuda_runtime.h>
#include <cuda_bf16.h>

#define D 784
#define H 1024
#define BATCH 1024
#define THREADS 128
#define HPT 8   // h-values per thread (128*8 = 1024 = H)

// Scratch (no allocations allowed): transposed W.
__device__ float g_WT[D * H];   // g_WT[i*H + h] = W[h*D + i]

__device__ __forceinline__ float fast_tanh(float x) {
    float y;
    asm("tanh.approx.f32 %0, %1;" : "=f"(y) : "f"(x));
    return y;
}

// ---------------------------------------------------------------------------
// Prep: tiled transpose W[H,D] -> g_WT[D,H]
// ---------------------------------------------------------------------------
__global__ void transpose_W(const float* __restrict__ W) {
    __shared__ float tile[32][33];
    int ix = blockIdx.x * 32 + threadIdx.x;   // D index (contiguous in W)
    int iy = blockIdx.y * 32 + threadIdx.y;   // H index
    #pragma unroll
    for (int j = 0; j < 32; j += 8) {
        int y = iy + j;
        if (ix < D && y < H)
            tile[threadIdx.y + j][threadIdx.x] = W[y * D + ix];
    }
    __syncthreads();
    int ox = blockIdx.y * 32 + threadIdx.x;   // H index (contiguous in WT)
    int oy = blockIdx.x * 32 + threadIdx.y;   // D index
    #pragma unroll
    for (int j = 0; j < 32; j += 8) {
        int y = oy + j;
        if (ox < H && y < D)
            g_WT[y * H + ox] = tile[threadIdx.x][threadIdx.y + j];
    }
}

// ---------------------------------------------------------------------------
// Main: one CTA per batch row. A = a/2 in registers (8/thread).
// Per step: t = tanh(A); sigma = fma(t, 0.5, 0.5) [FFMA-imm];
// p = dot(V_row, sigma) in two chains; A += WT_row * (x/2).
// 4-level xor shuffle -> 2 partials/warp -> deferred smem buffer.
// No __syncthreads inside the 784-step loop.
// ---------------------------------------------------------------------------
__global__ void __launch_bounds__(THREADS, 7)
nade_main(const float* __restrict__ pixels,
          const float* __restrict__ c,
          const float* __restrict__ V,
          const float* __restrict__ bvec,
          float* __restrict__ out) {
    __shared__ float sx[D];            // 0.5 * pixels[b, :]
    __shared__ float sp[D * 8];        // per-step partials: 4 warps x 2 lanes

    const int b    = blockIdx.x;
    const int t    = threadIdx.x;
    const int lane = t & 31;
    const int wid  = t >> 5;

    // Cooperative load of this row's pixels, pre-scaled by 0.5.
    for (int i = t; i < D; i += THREADS)
        sx[i] = 0.5f * pixels[b * D + i];

    // Accumulator init: A = c/2.
    float A[HPT];
    const float4* c4 = reinterpret_cast<const float4*>(c) + t * 2;
    {
        float4 c0 = c4[0];
        float4 c1 = c4[1];
        A[0] = 0.5f * c0.x; A[1] = 0.5f * c0.y; A[2] = 0.5f * c0.z; A[3] = 0.5f * c0.w;
        A[4] = 0.5f * c1.x; A[5] = 0.5f * c1.y; A[6] = 0.5f * c1.z; A[7] = 0.5f * c1.w;
    }
    __syncthreads();

    const float4* V4 = reinterpret_cast<const float4*>(V);
    const float4* W4 = reinterpret_cast<const float4*>(g_WT);
    const int base = t * 2;            // float4 index within a 256-float4 row
    const float half = 0.5f;

    #pragma unroll 2
    for (int i = 0; i < D; i++) {
        const int roff = i * (H / 4) + base;
        float4 v0 = V4[roff];
        float4 v1 = V4[roff + 1];
        float4 w0 = W4[roff];
        float4 w1 = W4[roff + 1];
        float xs = sx[i];

        float t0 = fast_tanh(A[0]);
        float t1 = fast_tanh(A[1]);
        float t2 = fast_tanh(A[2]);
        float t3 = fast_tanh(A[3]);
        float t4 = fast_tanh(A[4]);
        float t5 = fast_tanh(A[5]);
        float t6 = fast_tanh(A[6]);
        float t7 = fast_tanh(A[7]);

        // sigma = 0.5*t + 0.5  (FFMA with immediate multiplier -> rt1)
        float s0 = fmaf(t0, 0.5f, half);
        float s1 = fmaf(t1, 0.5f, half);
        float s2 = fmaf(t2, 0.5f, half);
        float s3 = fmaf(t3, 0.5f, half);
        float s4 = fmaf(t4, 0.5f, half);
        float s5 = fmaf(t5, 0.5f, half);
        float s6 = fmaf(t6, 0.5f, half);
        float s7 = fmaf(t7, 0.5f, half);

        // Two independent dot chains (shorter dependent depth).
        float pa = v0.x * s0;
        float pb = v1.x * s4;
        pa = fmaf(v0.y, s1, pa);
        pb = fmaf(v1.y, s5, pb);
        pa = fmaf(v0.z, s2, pa);
        pb = fmaf(v1.z, s6, pb);
        pa = fmaf(v0.w, s3, pa);
        pb = fmaf(v1.w, s7, pb);
        float p = pa + pb;

        A[0] = fmaf(w0.x, xs, A[0]);
        A[1] = fmaf(w0.y, xs, A[1]);
        A[2] = fmaf(w0.z, xs, A[2]);
        A[3] = fmaf(w0.w, xs, A[3]);
        A[4] = fmaf(w1.x, xs, A[4]);
        A[5] = fmaf(w1.y, xs, A[5]);
        A[6] = fmaf(w1.z, xs, A[6]);
        A[7] = fmaf(w1.w, xs, A[7]);

        // 4-level xor reduce: even lanes hold even-lane sum, odd lanes odd-lane sum.
        p += __shfl_xor_sync(0xffffffffu, p, 16);
        p += __shfl_xor_sync(0xffffffffu, p, 8);
        p += __shfl_xor_sync(0xffffffffu, p, 4);
        p += __shfl_xor_sync(0xffffffffu, p, 2);
        if (lane < 2) sp[i * 8 + wid * 2 + lane] = p;
    }

    __syncthreads();

    // Final cross-warp reduction + output: out[b,i] = b[i] + sum of 8 partials.
    for (int i = t; i < D; i += THREADS) {
        float s = (sp[i * 8 + 0] + sp[i * 8 + 1]) + (sp[i * 8 + 2] + sp[i * 8 + 3])
                + (sp[i * 8 + 4] + sp[i * 8 + 5]) + (sp[i * 8 + 6] + sp[i * 8 + 7]);
        out[b * D + i] = bvec[i] + s;
    }
}

// ---------------------------------------------------------------------------
extern "C" void kernel_launch(void* const* d_in, const int* in_sizes, int n_in,
                              void* d_out, int out_size) {
    const float* pixels = (const float*)d_in[0];   // [1024, 784]
    const float* W      = (const float*)d_in[1];   // [1024, 784]
    const float* c      = (const float*)d_in[2];   // [1024]
    const float* V      = (const float*)d_in[3];   // [784, 1024]
    const float* bvec   = (const float*)d_in[4];   // [784]
    float* out          = (float*)d_out;           // [1024, 784]

    dim3 tb(32, 8);
    dim3 tg((D + 31) / 32, H / 32);
    transpose_W<<<tg, tb>>>(W);
    nade_main<<<BATCH, THREADS>>>(pixels, c, V, bvec, out);
}

// round 4
// speedup vs baseline: 1.4430x; 1.3221x over previous
#include <cuda_runtime.h>
#include <cuda_bf16.h>

#define D 784
#define H 1024
#define BATCH 1024
#define THREADS 256
#define NPAIRS (BATCH / 2)          // 512 CTAs, 2 batch rows each
// smem: sx2[D] float2 (6272 B) + sp0[D*8] float (25088 B) + sp1[D*8] float (25088 B)
#define SMEM_BYTES (D * 8 + D * 8 * 4 + D * 8 * 4)

// Scratch (no allocations allowed): transposed W and fused bias.
__device__ float g_WT[D * H];   // g_WT[i*H + h] = W[h*D + i]
__device__ float g_bias[D];     // bias[i] = b[i] + 0.5 * sum_h V[i,h]

__device__ __forceinline__ float fast_tanh(float x) {
    float y;
    asm("tanh.approx.f32 %0, %1;" : "=f"(y) : "f"(x));
    return y;
}

// ---------------------------------------------------------------------------
// Prep 1: tiled transpose W[H,D] -> g_WT[D,H]
// ---------------------------------------------------------------------------
__global__ void transpose_W(const float* __restrict__ W) {
    __shared__ float tile[32][33];
    int ix = blockIdx.x * 32 + threadIdx.x;   // D index (contiguous in W)
    int iy = blockIdx.y * 32 + threadIdx.y;   // H index
    #pragma unroll
    for (int j = 0; j < 32; j += 8) {
        int y = iy + j;
        if (ix < D && y < H)
            tile[threadIdx.y + j][threadIdx.x] = W[y * D + ix];
    }
    __syncthreads();
    int ox = blockIdx.y * 32 + threadIdx.x;   // H index (contiguous in WT)
    int oy = blockIdx.x * 32 + threadIdx.y;   // D index
    #pragma unroll
    for (int j = 0; j < 32; j += 8) {
        int y = oy + j;
        if (ox < H && y < D)
            g_WT[y * H + ox] = tile[threadIdx.x][threadIdx.y + j];
    }
}

// ---------------------------------------------------------------------------
// Prep 2: bias[i] = b[i] + 0.5 * sum_h V[i,h]   (one warp per i)
// ---------------------------------------------------------------------------
__global__ void compute_bias(const float* __restrict__ V,
                             const float* __restrict__ bvec) {
    int i = blockIdx.x;
    int lane = threadIdx.x;
    float s = 0.0f;
    #pragma unroll
    for (int h = lane; h < H; h += 32) s += V[i * H + h];
    #pragma unroll
    for (int o = 16; o > 0; o >>= 1) s += __shfl_xor_sync(0xffffffffu, s, o);
    if (lane == 0) g_bias[i] = bvec[i] + 0.5f * s;
}

// ---------------------------------------------------------------------------
// Main: one CTA per PAIR of batch rows (amortizes V/W loads 2x).
// 256 threads; thread t owns h in [4t, 4t+4) for both rows.
// A = a/2 in registers (4 per row). Per step:
//   load v4, w4 once; 8x tanh; two 4-term dot chains; 8 accumulator FMAs;
//   combined 6-shuffle reduction of both rows; lane0/lane16 STS.
// No __syncthreads inside the 784-step loop.
// ---------------------------------------------------------------------------
__global__ void __launch_bounds__(THREADS, 4)
nade_main(const float* __restrict__ pixels,
          const float* __restrict__ c,
          const float* __restrict__ V,
          float* __restrict__ out) {
    extern __shared__ char smem_raw[];
    float2* sx2 = reinterpret_cast<float2*>(smem_raw);                 // [D]
    float*  sp0 = reinterpret_cast<float*>(smem_raw + D * 8);          // [D*8]
    float*  sp1 = reinterpret_cast<float*>(smem_raw + D * 8 + D * 32); // [D*8]

    const int bp = blockIdx.x;
    const int b0 = bp * 2, b1 = bp * 2 + 1;
    const int t = threadIdx.x;
    const int lane = t & 31;
    const int wid  = t >> 5;

    // Pixels for both rows, pre-scaled by 0.5, interleaved as float2.
    for (int i = t; i < D; i += THREADS)
        sx2[i] = make_float2(0.5f * pixels[b0 * D + i],
                             0.5f * pixels[b1 * D + i]);

    // Accumulators: A = c/2 (same init for both rows).
    float4 c4 = reinterpret_cast<const float4*>(c)[t];
    float a00 = 0.5f * c4.x, a01 = 0.5f * c4.y, a02 = 0.5f * c4.z, a03 = 0.5f * c4.w;
    float a10 = a00, a11 = a01, a12 = a02, a13 = a03;

    __syncthreads();

    const float4* V4 = reinterpret_cast<const float4*>(V);
    const float4* W4 = reinterpret_cast<const float4*>(g_WT);
    const bool lo_half = (lane < 16);

    #pragma unroll 2
    for (int i = 0; i < D; i++) {
        const int roff = i * (H / 4) + t;
        float4 v = V4[roff];
        float4 w = W4[roff];
        float2 xs = sx2[i];

        float t00 = fast_tanh(a00);
        float t01 = fast_tanh(a01);
        float t02 = fast_tanh(a02);
        float t03 = fast_tanh(a03);
        float t10 = fast_tanh(a10);
        float t11 = fast_tanh(a11);
        float t12 = fast_tanh(a12);
        float t13 = fast_tanh(a13);

        float p0 = v.x * t00;
        float p1 = v.x * t10;
        p0 = fmaf(v.y, t01, p0);
        p1 = fmaf(v.y, t11, p1);
        p0 = fmaf(v.z, t02, p0);
        p1 = fmaf(v.z, t12, p1);
        p0 = fmaf(v.w, t03, p0);
        p1 = fmaf(v.w, t13, p1);

        a00 = fmaf(w.x, xs.x, a00);
        a01 = fmaf(w.y, xs.x, a01);
        a02 = fmaf(w.z, xs.x, a02);
        a03 = fmaf(w.w, xs.x, a03);
        a10 = fmaf(w.x, xs.y, a10);
        a11 = fmaf(w.y, xs.y, a11);
        a12 = fmaf(w.z, xs.y, a12);
        a13 = fmaf(w.w, xs.y, a13);

        // Combined 2-row reduction: fold rows into lane halves (2 shuffles),
        // then 4 xor levels reduce both halves in parallel.
        float e0 = __shfl_xor_sync(0xffffffffu, p0, 16);
        float e1 = __shfl_xor_sync(0xffffffffu, p1, 16);
        float s = lo_half ? (p0 + e0) : (p1 + e1);
        s += __shfl_xor_sync(0xffffffffu, s, 8);
        s += __shfl_xor_sync(0xffffffffu, s, 4);
        s += __shfl_xor_sync(0xffffffffu, s, 2);
        s += __shfl_xor_sync(0xffffffffu, s, 1);
        if (lane == 0)  sp0[i * 8 + wid] = s;
        if (lane == 16) sp1[i * 8 + wid] = s;
    }

    __syncthreads();

    // Final cross-warp reduction + output.
    for (int i = t; i < D; i += THREADS) {
        float s0 = 0.0f, s1 = 0.0f;
        #pragma unroll
        for (int wi = 0; wi < 8; wi++) {
            s0 += sp0[i * 8 + wi];
            s1 += sp1[i * 8 + wi];
        }
        float bi = g_bias[i];
        out[b0 * D + i] = fmaf(0.5f, s0, bi);
        out[b1 * D + i] = fmaf(0.5f, s1, bi);
    }
}

// ---------------------------------------------------------------------------
extern "C" void kernel_launch(void* const* d_in, const int* in_sizes, int n_in,
                              void* d_out, int out_size) {
    const float* pixels = (const float*)d_in[0];   // [1024, 784]
    const float* W      = (const float*)d_in[1];   // [1024, 784]
    const float* c      = (const float*)d_in[2];   // [1024]
    const float* V      = (const float*)d_in[3];   // [784, 1024]
    const float* bvec   = (const float*)d_in[4];   // [784]
    float* out          = (float*)d_out;           // [1024, 784]

    // Allow full smem + carveout so 4 CTAs/SM fit (idempotent host calls).
    cudaFuncSetAttribute(nade_main, cudaFuncAttributeMaxDynamicSharedMemorySize,
                         SMEM_BYTES);
    cudaFuncSetAttribute(nade_main, cudaFuncAttributePreferredSharedMemoryCarveout,
                         100);

    dim3 tb(32, 8);
    dim3 tg((D + 31) / 32, H / 32);
    transpose_W<<<tg, tb>>>(W);
    compute_bias<<<D, 32>>>(V, bvec);
    nade_main<<<NPAIRS, THREADS, SMEM_BYTES>>>(pixels, c, V, out);
}

// round 5
// speedup vs baseline: 1.7908x; 1.2410x over previous
#include <cuda_runtime.h>
#include <cuda_bf16.h>
#include <cstdint>

#define D 784
#define H 1024
#define BATCH 1024
#define THREADS 256
#define NQUADS (BATCH / 4)          // 256 CTAs, 4 batch rows each
// smem: sx4[D] float4 (12544 B) + sp[D*8] float4 (100352 B)
#define SMEM_BYTES (D * 16 + D * 8 * 16)

// Scratch (no allocations allowed): transposed W and fused bias.
__device__ float g_WT[D * H];   // g_WT[i*H + h] = W[h*D + i]
__device__ float g_bias[D];     // bias[i] = b[i] + 0.5 * sum_h V[i,h]

// Two tanh evaluations in ONE MUFU op via f16x2. Errors ~2.4e-4 abs per value.
__device__ __forceinline__ void tanh2(float a, float b, float& ta, float& tb) {
    uint32_t pk, tk;
    asm("cvt.rn.f16x2.f32 %0, %1, %2;" : "=r"(pk) : "f"(b), "f"(a)); // lo=a, hi=b
    asm("tanh.approx.f16x2 %0, %1;" : "=r"(tk) : "r"(pk));
    asm("{\n\t.reg .b16 l, h;\n\t"
        "mov.b32 {l, h}, %2;\n\t"
        "cvt.f32.f16 %0, l;\n\t"
        "cvt.f32.f16 %1, h;\n\t}"
        : "=f"(ta), "=f"(tb) : "r"(tk));
}

// ---------------------------------------------------------------------------
// Fused prep: blockIdx.y < 32 -> tiled transpose W[H,D] -> g_WT[D,H]
//             blockIdx.y == 32 -> bias[i] = b[i] + 0.5 * sum_h V[i,h]
// ---------------------------------------------------------------------------
__global__ void prep_kernel(const float* __restrict__ W,
                            const float* __restrict__ V,
                            const float* __restrict__ bvec) {
    if (blockIdx.y < 32) {
        __shared__ float tile[32][33];
        int ix = blockIdx.x * 32 + threadIdx.x;   // D index
        int iy = blockIdx.y * 32 + threadIdx.y;   // H index
        #pragma unroll
        for (int j = 0; j < 32; j += 8) {
            int y = iy + j;
            if (ix < D && y < H)
                tile[threadIdx.y + j][threadIdx.x] = W[y * D + ix];
        }
        __syncthreads();
        int ox = blockIdx.y * 32 + threadIdx.x;   // H index
        int oy = blockIdx.x * 32 + threadIdx.y;   // D index
        #pragma unroll
        for (int j = 0; j < 32; j += 8) {
            int y = oy + j;
            if (ox < H && y < D)
                g_WT[y * H + ox] = tile[threadIdx.x][threadIdx.y + j];
        }
    } else {
        // 8 warps, each handles 4 consecutive i values.
        int lane = threadIdx.x;
        int w    = threadIdx.y;
        #pragma unroll
        for (int k = 0; k < 4; k++) {
            int i = blockIdx.x * 32 + w * 4 + k;
            if (i >= D) continue;
            float s = 0.0f;
            #pragma unroll
            for (int j = 0; j < H / 32; j++) s += V[i * H + j * 32 + lane];
            #pragma unroll
            for (int o = 16; o > 0; o >>= 1)
                s += __shfl_xor_sync(0xffffffffu, s, o);
            if (lane == 0) g_bias[i] = bvec[i] + 0.5f * s;
        }
    }
}

// ---------------------------------------------------------------------------
// Main: one CTA per QUAD of batch rows (amortizes V/W loads 4x).
// 256 threads; thread t owns h in [4t, 4t+4) for all 4 rows (16 accumulators).
// Per step: load v4, w4 once; 8x tanh.f16x2 (16 tanh); 4 dot chains;
// 16 accumulator FMAs; combined 9-shuffle 4-row reduction; predicated STS.
// No __syncthreads inside the 784-step loop.
// ---------------------------------------------------------------------------
__global__ void __launch_bounds__(THREADS, 2)
nade_main(const float* __restrict__ pixels,
          const float* __restrict__ c,
          const float* __restrict__ V,
          float* __restrict__ out) {
    extern __shared__ char smem_raw[];
    float4* sx4 = reinterpret_cast<float4*>(smem_raw);            // [D]
    float4* sp4 = reinterpret_cast<float4*>(smem_raw + D * 16);   // [D*8]

    const int bq = blockIdx.x;
    const int b0 = bq * 4;
    const int t = threadIdx.x;
    const int lane = t & 31;
    const int wid  = t >> 5;

    // Pixels for all 4 rows, pre-scaled by 0.5.
    for (int i = t; i < D; i += THREADS)
        sx4[i] = make_float4(0.5f * pixels[(b0 + 0) * D + i],
                             0.5f * pixels[(b0 + 1) * D + i],
                             0.5f * pixels[(b0 + 2) * D + i],
                             0.5f * pixels[(b0 + 3) * D + i]);

    // Accumulators: A = c/2 (same init for all rows).
    float4 c4 = reinterpret_cast<const float4*>(c)[t];
    float a00 = 0.5f * c4.x, a01 = 0.5f * c4.y, a02 = 0.5f * c4.z, a03 = 0.5f * c4.w;
    float a10 = a00, a11 = a01, a12 = a02, a13 = a03;
    float a20 = a00, a21 = a01, a22 = a02, a23 = a03;
    float a30 = a00, a31 = a01, a32 = a02, a33 = a03;

    __syncthreads();

    const float4* V4 = reinterpret_cast<const float4*>(V);
    const float4* W4 = reinterpret_cast<const float4*>(g_WT);
    const int row_sel = ((lane >> 3) & 1) * 2 + (lane >> 4);  // 0,2,1,3 @ lanes 0,8,16,24
    const bool is_head = (lane & 7) == 0;

    #pragma unroll 2
    for (int i = 0; i < D; i++) {
        const int roff = i * (H / 4) + t;
        float4 v = V4[roff];
        float4 w = W4[roff];
        float4 xs = sx4[i];

        float t00, t01, t02, t03, t10, t11, t12, t13;
        float t20, t21, t22, t23, t30, t31, t32, t33;
        tanh2(a00, a01, t00, t01);
        tanh2(a02, a03, t02, t03);
        tanh2(a10, a11, t10, t11);
        tanh2(a12, a13, t12, t13);
        tanh2(a20, a21, t20, t21);
        tanh2(a22, a23, t22, t23);
        tanh2(a30, a31, t30, t31);
        tanh2(a32, a33, t32, t33);

        float p0 = v.x * t00;
        float p1 = v.x * t10;
        float p2 = v.x * t20;
        float p3 = v.x * t30;
        p0 = fmaf(v.y, t01, p0);
        p1 = fmaf(v.y, t11, p1);
        p2 = fmaf(v.y, t21, p2);
        p3 = fmaf(v.y, t31, p3);
        p0 = fmaf(v.z, t02, p0);
        p1 = fmaf(v.z, t12, p1);
        p2 = fmaf(v.z, t22, p2);
        p3 = fmaf(v.z, t32, p3);
        p0 = fmaf(v.w, t03, p0);
        p1 = fmaf(v.w, t13, p1);
        p2 = fmaf(v.w, t23, p2);
        p3 = fmaf(v.w, t33, p3);

        a00 = fmaf(w.x, xs.x, a00);
        a01 = fmaf(w.y, xs.x, a01);
        a02 = fmaf(w.z, xs.x, a02);
        a03 = fmaf(w.w, xs.x, a03);
        a10 = fmaf(w.x, xs.y, a10);
        a11 = fmaf(w.y, xs.y, a11);
        a12 = fmaf(w.z, xs.y, a12);
        a13 = fmaf(w.w, xs.y, a13);
        a20 = fmaf(w.x, xs.z, a20);
        a21 = fmaf(w.y, xs.z, a21);
        a22 = fmaf(w.z, xs.z, a22);
        a23 = fmaf(w.w, xs.z, a23);
        a30 = fmaf(w.x, xs.w, a30);
        a31 = fmaf(w.y, xs.w, a31);
        a32 = fmaf(w.z, xs.w, a32);
        a33 = fmaf(w.w, xs.w, a33);

        // Combined 4-row reduction: 9 shuffles total.
        float e0 = __shfl_xor_sync(0xffffffffu, p0, 16);
        float e1 = __shfl_xor_sync(0xffffffffu, p1, 16);
        bool lo16 = (lane & 16) == 0;
        float sA = lo16 ? (p0 + e0) : (p1 + e1);
        float e2 = __shfl_xor_sync(0xffffffffu, p2, 16);
        float e3 = __shfl_xor_sync(0xffffffffu, p3, 16);
        float sB = lo16 ? (p2 + e2) : (p3 + e3);

        float eA = __shfl_xor_sync(0xffffffffu, sA, 8);
        float eB = __shfl_xor_sync(0xffffffffu, sB, 8);
        float s = ((lane & 8) == 0) ? (sA + eA) : (sB + eB);

        s += __shfl_xor_sync(0xffffffffu, s, 4);
        s += __shfl_xor_sync(0xffffffffu, s, 2);
        s += __shfl_xor_sync(0xffffffffu, s, 1);

        // lanes 0,8,16,24 hold row sums for rows 0,2,1,3.
        if (is_head)
            reinterpret_cast<float*>(&sp4[i * 8 + wid])[row_sel] = s;
    }

    __syncthreads();

    // Final cross-warp reduction + output.
    for (int i = t; i < D; i += THREADS) {
        float4 s = make_float4(0.f, 0.f, 0.f, 0.f);
        #pragma unroll
        for (int wi = 0; wi < 8; wi++) {
            float4 q = sp4[i * 8 + wi];
            s.x += q.x; s.y += q.y; s.z += q.z; s.w += q.w;
        }
        float bi = g_bias[i];
        out[(b0 + 0) * D + i] = fmaf(0.5f, s.x, bi);
        out[(b0 + 1) * D + i] = fmaf(0.5f, s.y, bi);
        out[(b0 + 2) * D + i] = fmaf(0.5f, s.z, bi);
        out[(b0 + 3) * D + i] = fmaf(0.5f, s.w, bi);
    }
}

// ---------------------------------------------------------------------------
extern "C" void kernel_launch(void* const* d_in, const int* in_sizes, int n_in,
                              void* d_out, int out_size) {
    const float* pixels = (const float*)d_in[0];   // [1024, 784]
    const float* W      = (const float*)d_in[1];   // [1024, 784]
    const float* c      = (const float*)d_in[2];   // [1024]
    const float* V      = (const float*)d_in[3];   // [784, 1024]
    const float* bvec   = (const float*)d_in[4];   // [784]
    float* out          = (float*)d_out;           // [1024, 784]

    cudaFuncSetAttribute(nade_main, cudaFuncAttributeMaxDynamicSharedMemorySize,
                         SMEM_BYTES);
    cudaFuncSetAttribute(nade_main, cudaFuncAttributePreferredSharedMemoryCarveout,
                         100);

    prep_kernel<<<dim3(25, 33), dim3(32, 8)>>>(W, V, bvec);
    nade_main<<<NQUADS, THREADS, SMEM_BYTES>>>(pixels, c, V, out);
}

// round 6
// speedup vs baseline: 1.8302x; 1.0220x over previous
#include <cuda_runtime.h>
#include <cuda_bf16.h>
#include <cstdint>

#define D 784
#define H 1024
#define BATCH 1024
#define THREADS 512
#define R 7                      // batch rows per CTA
#define NCTAS 147                // 147*7 = 1029 >= 1024
#define CHUNK 98                 // 784 = 8 * 98
#define NCHUNKS (D / CHUNK)
#define SX_BYTES (D * 8 * 4)                 // sx8[D][8]
#define SP_BYTES (CHUNK * 16 * 8 * 4)        // sp[CHUNK][16][8]
#define SMEM_BYTES (SX_BYTES + SP_BYTES)     // 75264

// Scratch (no allocations allowed): transposed W and fused bias.
__device__ float g_WT[D * H];   // g_WT[i*H + h] = W[h*D + i]
__device__ float g_bias[D];     // bias[i] = b[i] + 0.5 * sum_h V[i,h]

// Two tanh evaluations in ONE MUFU op via f16x2.
__device__ __forceinline__ void tanh2(float a, float b, float& ta, float& tb) {
    uint32_t pk, tk;
    asm("cvt.rn.f16x2.f32 %0, %1, %2;" : "=r"(pk) : "f"(b), "f"(a)); // lo=a, hi=b
    asm("tanh.approx.f16x2 %0, %1;" : "=r"(tk) : "r"(pk));
    asm("{\n\t.reg .b16 l, h;\n\t"
        "mov.b32 {l, h}, %2;\n\t"
        "cvt.f32.f16 %0, l;\n\t"
        "cvt.f32.f16 %1, h;\n\t}"
        : "=f"(ta), "=f"(tb) : "r"(tk));
}

// ---------------------------------------------------------------------------
// Fused prep: blockIdx.y < 32 -> tiled transpose W[H,D] -> g_WT[D,H]
//             blockIdx.y == 32 -> bias[i] = b[i] + 0.5 * sum_h V[i,h]
// ---------------------------------------------------------------------------
__global__ void prep_kernel(const float* __restrict__ W,
                            const float* __restrict__ V,
                            const float* __restrict__ bvec) {
    if (blockIdx.y < 32) {
        __shared__ float tile[32][33];
        int ix = blockIdx.x * 32 + threadIdx.x;   // D index
        int iy = blockIdx.y * 32 + threadIdx.y;   // H index
        #pragma unroll
        for (int j = 0; j < 32; j += 8) {
            int y = iy + j;
            if (ix < D && y < H)
                tile[threadIdx.y + j][threadIdx.x] = W[y * D + ix];
        }
        __syncthreads();
        int ox = blockIdx.y * 32 + threadIdx.x;   // H index
        int oy = blockIdx.x * 32 + threadIdx.y;   // D index
        #pragma unroll
        for (int j = 0; j < 32; j += 8) {
            int y = oy + j;
            if (ox < H && y < D)
                g_WT[y * H + ox] = tile[threadIdx.x][threadIdx.y + j];
        }
    } else {
        int lane = threadIdx.x;
        int w    = threadIdx.y;
        #pragma unroll
        for (int k = 0; k < 4; k++) {
            int i = blockIdx.x * 32 + w * 4 + k;
            if (i >= D) continue;
            float s = 0.0f;
            #pragma unroll
            for (int j = 0; j < H / 32; j++) s += V[i * H + j * 32 + lane];
            #pragma unroll
            for (int o = 16; o > 0; o >>= 1)
                s += __shfl_xor_sync(0xffffffffu, s, o);
            if (lane == 0) g_bias[i] = bvec[i] + 0.5f * s;
        }
    }
}

// ---------------------------------------------------------------------------
// Main: one CTA per 7 batch rows; 512 threads (16 warps), 2 h per lane.
// A = a/2 in float2 registers (7 per thread). Per step per warp:
//   LDG.64 v + LDG.64 w; 2x LDS.128 xs; 7 tanh2; 14 dot FMA; 14 acc FMA;
//   16-shuffle combined 8-slot butterfly; 1 predicated STS.
// Partials deferred per 98-step chunk, then cross-warp reduced + stored.
// ---------------------------------------------------------------------------
__global__ void __launch_bounds__(THREADS, 1)
nade_main(const float* __restrict__ pixels,
          const float* __restrict__ c,
          const float* __restrict__ V,
          float* __restrict__ out) {
    extern __shared__ char smem_raw[];
    float* sx8 = reinterpret_cast<float*>(smem_raw);              // [D][8]
    float* sp  = reinterpret_cast<float*>(smem_raw + SX_BYTES);   // [CHUNK][16][8]

    const int b0   = blockIdx.x * R;
    const int t    = threadIdx.x;
    const int lane = t & 31;
    const int wid  = t >> 5;

    for (int i = t; i < D; i += THREADS) {
        #pragma unroll
        for (int r = 0; r < R; r++) {
            int br = min(b0 + r, BATCH - 1);
            sx8[i * 8 + r] = 0.5f * pixels[br * D + i];
        }
        sx8[i * 8 + 7] = 0.0f;
    }

    float2 A[R];
    {
        float2 cc = reinterpret_cast<const float2*>(c)[t];
        cc.x *= 0.5f; cc.y *= 0.5f;
        #pragma unroll
        for (int r = 0; r < R; r++) A[r] = cc;
    }
    __syncthreads();

    const bool lo16 = (lane & 16) == 0;
    const bool lo8  = (lane & 8)  == 0;
    const bool lo4  = (lane & 4)  == 0;
    const int rowmap = ((lane >> 4) & 1) | (((lane >> 3) & 1) << 1)
                     | (((lane >> 2) & 1) << 2);
    const bool is_head = (lane & 3) == 0;

    const float2* __restrict__ V2 = reinterpret_cast<const float2*>(V);
    const float2* __restrict__ W2 = reinterpret_cast<const float2*>(g_WT);

    for (int ch = 0; ch < NCHUNKS; ch++) {
        const int ibase = ch * CHUNK;

        #pragma unroll 2
        for (int il = 0; il < CHUNK; il++) {
            const int i = ibase + il;
            const int roff = i * (H / 2) + t;
            float2 v = V2[roff];
            float2 w = W2[roff];
            const float4* xs4 = reinterpret_cast<const float4*>(&sx8[i * 8]);
            float4 x03 = xs4[0];
            float4 x47 = xs4[1];

            float p0, p1, p2, p3, p4, p5, p6;
            {
                float t0, t1;
                tanh2(A[0].x, A[0].y, t0, t1); p0 = fmaf(v.y, t1, v.x * t0);
                tanh2(A[1].x, A[1].y, t0, t1); p1 = fmaf(v.y, t1, v.x * t0);
                tanh2(A[2].x, A[2].y, t0, t1); p2 = fmaf(v.y, t1, v.x * t0);
                tanh2(A[3].x, A[3].y, t0, t1); p3 = fmaf(v.y, t1, v.x * t0);
                tanh2(A[4].x, A[4].y, t0, t1); p4 = fmaf(v.y, t1, v.x * t0);
                tanh2(A[5].x, A[5].y, t0, t1); p5 = fmaf(v.y, t1, v.x * t0);
                tanh2(A[6].x, A[6].y, t0, t1); p6 = fmaf(v.y, t1, v.x * t0);
            }

            A[0].x = fmaf(w.x, x03.x, A[0].x);
            A[0].y = fmaf(w.y, x03.x, A[0].y);
            A[1].x = fmaf(w.x, x03.y, A[1].x);
            A[1].y = fmaf(w.y, x03.y, A[1].y);
            A[2].x = fmaf(w.x, x03.z, A[2].x);
            A[2].y = fmaf(w.y, x03.z, A[2].y);
            A[3].x = fmaf(w.x, x03.w, A[3].x);
            A[3].y = fmaf(w.y, x03.w, A[3].y);
            A[4].x = fmaf(w.x, x47.x, A[4].x);
            A[4].y = fmaf(w.y, x47.x, A[4].y);
            A[5].x = fmaf(w.x, x47.y, A[5].x);
            A[5].y = fmaf(w.y, x47.y, A[5].y);
            A[6].x = fmaf(w.x, x47.z, A[6].x);
            A[6].y = fmaf(w.y, x47.z, A[6].y);

            // 8-slot combined butterfly: 16 shuffles for 7 rows (+1 dummy).
            float e, f;
            e = __shfl_xor_sync(0xffffffffu, p0, 16);
            f = __shfl_xor_sync(0xffffffffu, p1, 16);
            float q01 = lo16 ? (p0 + e) : (p1 + f);
            e = __shfl_xor_sync(0xffffffffu, p2, 16);
            f = __shfl_xor_sync(0xffffffffu, p3, 16);
            float q23 = lo16 ? (p2 + e) : (p3 + f);
            e = __shfl_xor_sync(0xffffffffu, p4, 16);
            f = __shfl_xor_sync(0xffffffffu, p5, 16);
            float q45 = lo16 ? (p4 + e) : (p5 + f);
            e = __shfl_xor_sync(0xffffffffu, p6, 16);
            float q67 = lo16 ? (p6 + e) : 0.0f;   // slot 7 is zero

            e = __shfl_xor_sync(0xffffffffu, q01, 8);
            f = __shfl_xor_sync(0xffffffffu, q23, 8);
            float q0123 = lo8 ? (q01 + e) : (q23 + f);
            e = __shfl_xor_sync(0xffffffffu, q45, 8);
            f = __shfl_xor_sync(0xffffffffu, q67, 8);
            float q4567 = lo8 ? (q45 + e) : (q67 + f);

            e = __shfl_xor_sync(0xffffffffu, q0123, 4);
            f = __shfl_xor_sync(0xffffffffu, q4567, 4);
            float qq = lo4 ? (q0123 + e) : (q4567 + f);

            qq += __shfl_xor_sync(0xffffffffu, qq, 2);
            qq += __shfl_xor_sync(0xffffffffu, qq, 1);

            if (is_head) sp[(il * 16 + wid) * 8 + rowmap] = qq;
        }

        __syncthreads();

        // Cross-warp reduction for this chunk + output.
        for (int o = t; o < CHUNK * R; o += THREADS) {
            int il = o / R, r = o % R;
            float s = 0.0f;
            #pragma unroll
            for (int wi = 0; wi < 16; wi++)
                s += sp[(il * 16 + wi) * 8 + r];
            int i = ibase + il;
            int b = b0 + r;
            if (b < BATCH) out[b * D + i] = fmaf(0.5f, s, g_bias[i]);
        }

        __syncthreads();
    }
}

// ---------------------------------------------------------------------------
extern "C" void kernel_launch(void* const* d_in, const int* in_sizes, int n_in,
                              void* d_out, int out_size) {
    const float* pixels = (const float*)d_in[0];   // [1024, 784]
    const float* W      = (const float*)d_in[1];   // [1024, 784]
    const float* c      = (const float*)d_in[2];   // [1024]
    const float* V      = (const float*)d_in[3];   // [784, 1024]
    const float* bvec   = (const float*)d_in[4];   // [784]
    float* out          = (float*)d_out;           // [1024, 784]

    cudaFuncSetAttribute(nade_main, cudaFuncAttributeMaxDynamicSharedMemorySize,
                         SMEM_BYTES);
    cudaFuncSetAttribute(nade_main, cudaFuncAttributePreferredSharedMemoryCarveout,
                         100);

    prep_kernel<<<dim3(25, 33), dim3(32, 8)>>>(W, V, bvec);
    nade_main<<<NCTAS, THREADS, SMEM_BYTES>>>(pixels, c, V, out);
}